// round 7
// baseline (speedup 1.0000x reference)
#include <cuda_runtime.h>
#include <math_constants.h>

// Scratch for segment offsets (allocation-free rule: __device__ global).
__device__ int g_offsets[65537];

// ---------------------------------------------------------------------------
// Kernel 1: vectorized streaming boundary scan over the SORTED segment_ids.
// Each thread owns 8 consecutive ids (two int4 loads / four longlong2 loads)
// plus one scalar successor probe; interior transitions resolve in registers.
// At each transition id -> next the thread fills g_offsets for every segment
// in (id, next]. Thread of element 0 fills the head; the last element fills
// the tail up to G. Handles int64 (reference dtype) and int32 (JAX default)
// via an on-device dtype sniff.
// ---------------------------------------------------------------------------
__global__ void seg_boundaries_kernel(const void* __restrict__ seg, int n, int G) {
    const int base = (blockIdx.x * blockDim.x + threadIdx.x) * 8;
    if (base >= n) return;

    // dtype sniff (warp-uniform): int64 word at index n/4 covers int32
    // elements n/2, n/2+1. Sorted ids: middle element ~G/2 != 0, so int32
    // data read as int64 is >= 2^32; genuine int64 data stays a small id.
    const long long probe = ((const long long*)seg)[n >> 2];
    const bool is64 = (probe >= 0) && (probe < (1LL << 31));

    int v[9];  // 8 owned ids + successor (sentinel G past the end)
    if (base + 8 <= n) {
        if (is64) {
            const longlong2* p = (const longlong2*)((const long long*)seg + base);
            #pragma unroll
            for (int j = 0; j < 4; j++) {
                longlong2 a = __ldg(&p[j]);
                v[2 * j]     = (int)a.x;
                v[2 * j + 1] = (int)a.y;
            }
        } else {
            const int4* p = (const int4*)((const int*)seg + base);
            int4 a = __ldg(&p[0]);
            int4 b = __ldg(&p[1]);
            v[0] = a.x; v[1] = a.y; v[2] = a.z; v[3] = a.w;
            v[4] = b.x; v[5] = b.y; v[6] = b.z; v[7] = b.w;
        }
        v[8] = (base + 8 < n)
                 ? (is64 ? (int)((const long long*)seg)[base + 8]
                         : ((const int*)seg)[base + 8])
                 : G;
    } else {
        // ragged tail: scalar loads, pad with sentinel G
        #pragma unroll
        for (int j = 0; j < 9; j++) {
            const int idx = base + j;
            v[j] = (idx < n)
                     ? (is64 ? (int)((const long long*)seg)[idx]
                             : ((const int*)seg)[idx])
                     : G;
        }
    }

    if (base == 0) {
        for (int g = 0; g <= v[0]; g++) g_offsets[g] = 0;
    }
    #pragma unroll
    for (int j = 0; j < 8; j++) {
        // first row of every segment in (v[j], v[j+1]] is base+j+1
        for (int g = v[j] + 1; g <= v[j + 1]; g++) g_offsets[g] = base + j + 1;
    }
}

// ---------------------------------------------------------------------------
// Kernel 2: one block per segment. 128 threads = 4 row-groups x 32 lanes.
// Lane l owns features [4l, 4l+4) via float4 (coalesced LDG.128, streaming
// hint). Row-group r processes rows start+r, start+r+4, ... Cross-group
// combine in shared memory; in the epilogue thread (stat s, lane l) combines
// its stat componentwise and writes ONE float4 streaming store.
// smem stat order matches output order: 0=max, 1=min, 2=sum, 3=sumsq.
// ---------------------------------------------------------------------------
__global__ void __launch_bounds__(128, 12)
seg_pool_kernel(const float* __restrict__ x, float* __restrict__ out, int G) {
    const int g = blockIdx.x;
    const int start = g_offsets[g];
    const int end   = g_offsets[g + 1];

    const int lane = threadIdx.x & 31;
    const int grp  = threadIdx.x >> 5;

    float4 s  = make_float4(0.f, 0.f, 0.f, 0.f);
    float4 q  = make_float4(0.f, 0.f, 0.f, 0.f);
    float4 mx = make_float4(-CUDART_INF_F, -CUDART_INF_F, -CUDART_INF_F, -CUDART_INF_F);
    float4 mn = make_float4( CUDART_INF_F,  CUDART_INF_F,  CUDART_INF_F,  CUDART_INF_F);

    const float4* __restrict__ xv = (const float4*)x;  // row stride = 32 float4

    #pragma unroll 4
    for (int r = start + grp; r < end; r += 4) {
        float4 v = __ldcs(&xv[(size_t)r * 32 + lane]);
        s.x += v.x; s.y += v.y; s.z += v.z; s.w += v.w;
        q.x = fmaf(v.x, v.x, q.x); q.y = fmaf(v.y, v.y, q.y);
        q.z = fmaf(v.z, v.z, q.z); q.w = fmaf(v.w, v.w, q.w);
        mx.x = fmaxf(mx.x, v.x); mx.y = fmaxf(mx.y, v.y);
        mx.z = fmaxf(mx.z, v.z); mx.w = fmaxf(mx.w, v.w);
        mn.x = fminf(mn.x, v.x); mn.y = fminf(mn.y, v.y);
        mn.z = fminf(mn.z, v.z); mn.w = fminf(mn.w, v.w);
    }

    // partials: [stat][group][lane] as float4 -> 4*4*32*16B = 8 KB
    // stat order = output order: 0=max, 1=min, 2=sum(->mean), 3=sumsq(->std)
    __shared__ float4 sm4[4][4][32];
    sm4[0][grp][lane] = mx;
    sm4[1][grp][lane] = mn;
    sm4[2][grp][lane] = s;
    sm4[3][grp][lane] = q;
    __syncthreads();

    // epilogue: thread (stat st=grp, lane l) combines the 4 group partials
    // for features [4l, 4l+4) of its stat and writes one float4.
    const int st = grp;
    const int l  = lane;
    const float cnt = (float)(end - start);

    float4 r = sm4[st][0][l];
    if (st == 0) {
        #pragma unroll
        for (int k = 1; k < 4; k++) {
            float4 t = sm4[0][k][l];
            r.x = fmaxf(r.x, t.x); r.y = fmaxf(r.y, t.y);
            r.z = fmaxf(r.z, t.z); r.w = fmaxf(r.w, t.w);
        }
    } else if (st == 1) {
        #pragma unroll
        for (int k = 1; k < 4; k++) {
            float4 t = sm4[1][k][l];
            r.x = fminf(r.x, t.x); r.y = fminf(r.y, t.y);
            r.z = fminf(r.z, t.z); r.w = fminf(r.w, t.w);
        }
    } else if (st == 2) {
        #pragma unroll
        for (int k = 1; k < 4; k++) {
            float4 t = sm4[2][k][l];
            r.x += t.x; r.y += t.y; r.z += t.z; r.w += t.w;
        }
        r.x /= cnt; r.y /= cnt; r.z /= cnt; r.w /= cnt;  // mean
    } else {
        float4 su = sm4[2][0][l];
        #pragma unroll
        for (int k = 1; k < 4; k++) {
            float4 tq = sm4[3][k][l];
            float4 ts = sm4[2][k][l];
            r.x += tq.x; r.y += tq.y; r.z += tq.z; r.w += tq.w;
            su.x += ts.x; su.y += ts.y; su.z += ts.z; su.w += ts.w;
        }
        const float inv = 1.0f / cnt;
        const float mx_ = su.x * inv, my_ = su.y * inv,
                    mz_ = su.z * inv, mw_ = su.w * inv;
        const float d = cnt - 1.0f;
        r.x = sqrtf(fmaxf((r.x - cnt * mx_ * mx_) / d, 0.0f));
        r.y = sqrtf(fmaxf((r.y - cnt * my_ * my_) / d, 0.0f));
        r.z = sqrtf(fmaxf((r.z - cnt * mz_ * mz_) / d, 0.0f));
        r.w = sqrtf(fmaxf((r.w - cnt * mw_ * mw_) / d, 0.0f));
    }

    // out[g][st][4l .. 4l+4): one coalesced 16B streaming store per thread
    float4* o4 = (float4*)(out + (size_t)g * 512 + st * 128);
    __stcs(&o4[l], r);
}

extern "C" void kernel_launch(void* const* d_in, const int* in_sizes, int n_in,
                              void* d_out, int out_size) {
    const float* x   = (const float*)d_in[0];
    const void*  seg = d_in[1];
    float* out = (float*)d_out;

    const int D = 128;
    const int n = in_sizes[0] / D;          // number of rows
    const int G = out_size / (4 * D);       // number of segments

    const int elems_per_thread = 8;
    const int tb = 256;
    const int work = (n + elems_per_thread - 1) / elems_per_thread;
    const int nb = (work + tb - 1) / tb;
    seg_boundaries_kernel<<<nb, tb>>>(seg, n, G);
    seg_pool_kernel<<<G, 128>>>(x, out, G);
}